// round 9
// baseline (speedup 1.0000x reference)
#include <cuda_runtime.h>
#include <cuda_bf16.h>

// Problem constants
#define BB 8
#define NN 65536
#define PP 12
#define GG 64
#define G3 (GG*GG*GG)               // 262144
#define THREADS 256
#define NBLOCKS ((BB*NN)/THREADS)   // 2048

// Scratch (static device arrays — no dynamic allocation anywhere)
__device__ float g_partials[NBLOCKS];
__device__ int   g_counter = 0;     // last-block ticket; self-resets each launch

// ---------------------------------------------------------------------------
// Single fused kernel. One thread per (b, point); each thread owns the 12
// flat positions f = pt*12+k of the reference's (b, p*n) flattening, so
// plane = f >> 16 (N = 2^16)  — reproduces the reference's reshape
// reinterpretation of the broadcast (b,n,p,3) array into (b,p,n,3).
//
// R8 lesson: occupancy is not the binding constraint; L1tex wavefronts from
// random gathers are. This round: cp row (12B) fetched via 1 aligned
// LDG.128 (+1 predicated LDG.128 for the ~50% of lanes whose row straddles a
// 16B boundary) with exact select extraction, instead of 3 LDG.32.
//
// Planes normalized once per block in shared with EXACT reference arithmetic
// (sqrtf + division) — R5 proved approximate normalization flips ceil cells.
// Phase B recomputes s from the same shared values with the same expression
// (bit-identical; validated in R8).
// ---------------------------------------------------------------------------
__global__ __launch_bounds__(THREADS, 6)
void sym_plane_loss_kernel(const float* __restrict__ voxel,
                           const float* __restrict__ points,
                           const float* __restrict__ cp,
                           const float* __restrict__ planes,
                           float* __restrict__ out)
{
    const int t  = blockIdx.x * THREADS + threadIdx.x;   // 0 .. B*N-1
    const int b  = t >> 16;            // N = 65536; constant within a block
    const int pt = t & 0xFFFF;

    // ---- normalize this batch's 12 planes into shared (exact math) ----
    __shared__ float4 s_planes[PP];
    if (threadIdx.x < PP) {
        const int i = b * PP + threadIdx.x;
        const float nx = planes[i*4+0];
        const float ny = planes[i*4+1];
        const float nz = planes[i*4+2];
        const float d  = planes[i*4+3];
        const float norm = sqrtf(nx*nx + ny*ny + nz*nz);
        s_planes[threadIdx.x] = make_float4(nx/norm, ny/norm, nz/norm, d/norm);
    }
    __syncthreads();

    const float px = __ldg(points + t*3 + 0);
    const float py = __ldg(points + t*3 + 1);
    const float pz = __ldg(points + t*3 + 2);

    const float*  __restrict__ vox_b = voxel + b * G3;
    const float4* __restrict__ cp4_b = (const float4*)(cp + (size_t)b * G3 * 3);

    const int base_f = pt * PP;

    int idxs[PP];

    // ---- Phase A: reflections + indices ----
    #pragma unroll
    for (int k = 0; k < PP; k++) {
        const int f     = base_f + k;
        const float4 n4 = s_planes[f >> 16];

        const float dot = px*n4.x + py*n4.y + pz*n4.z;
        const float s   = 2.0f * (dot + n4.w);
        const float rx  = px - s * n4.x;
        const float ry  = py - s * n4.y;
        const float rz  = pz - s * n4.z;

        const int ix = (int)ceilf(__fadd_rn(__fmul_rn(__fadd_rn(rx, 0.5f), (float)GG), -0.5f));
        const int iy = (int)ceilf(__fadd_rn(__fmul_rn(__fadd_rn(ry, 0.5f), (float)GG), -0.5f));
        const int iz = (int)ceilf(__fadd_rn(__fmul_rn(__fadd_rn(rz, 0.5f), (float)GG), -0.5f));

        int idx = ix * (GG*GG) + iy * GG + iz;
        idx = min(max(idx, 0), G3 - 1);
        idxs[k] = idx;
    }

    // ---- batched voxel gathers -> one occupancy bit-word (MLP=12) ----
    unsigned occ = 0;
    #pragma unroll
    for (int k = 0; k < PP; k++) {
        const float v = __ldg(vox_b + idxs[k]);
        occ |= (v != 0.0f ? 1u : 0u) << k;
    }

    // ---- Phase B: masked cp gathers (float4 trick) + accumulate ----
    float acc = 0.0f;
    #pragma unroll
    for (int k = 0; k < PP; k++) {
        if (!((occ >> k) & 1u)) {
            const int f     = base_f + k;
            const float4 n4 = s_planes[f >> 16];
            const float dot = px*n4.x + py*n4.y + pz*n4.z;   // identical expr as Phase A
            const float s   = 2.0f * (dot + n4.w);
            const float rx  = px - s * n4.x;
            const float ry  = py - s * n4.y;
            const float rz  = pz - s * n4.z;

            const int idx = idxs[k];
            const int f0  = idx * 3;          // float offset of cp row
            const int e0  = f0 >> 2;          // float4 index
            const int off = f0 & 3;           // 0..3

            float4 q0 = __ldg(cp4_b + e0);
            float4 q1 = q0;                   // defined even when not loaded
            if (off >= 2) q1 = __ldg(cp4_b + e0 + 1);   // predicated, ~50% lanes

            // exact component extraction (selects only; values untouched)
            const float cx = (off == 0) ? q0.x : (off == 1) ? q0.y : (off == 2) ? q0.z : q0.w;
            const float cy = (off == 0) ? q0.y : (off == 1) ? q0.z : (off == 2) ? q0.w : q1.x;
            const float cz = (off == 0) ? q0.z : (off == 1) ? q0.w : (off == 2) ? q1.x : q1.y;

            const float dx = rx - cx;
            const float dy = ry - cy;
            const float dz = rz - cz;
            acc += dx*dx + dy*dy + dz*dz;
        }
    }

    // ---- deterministic block reduction ----
    __shared__ float sdata[THREADS];
    __shared__ bool  s_is_last;
    sdata[threadIdx.x] = acc;
    __syncthreads();
    #pragma unroll
    for (int stride = THREADS/2; stride >= 32; stride >>= 1) {
        if (threadIdx.x < stride) sdata[threadIdx.x] += sdata[threadIdx.x + stride];
        __syncthreads();
    }
    if (threadIdx.x < 32) {
        float w = sdata[threadIdx.x];
        #pragma unroll
        for (int off = 16; off > 0; off >>= 1)
            w += __shfl_down_sync(0xFFFFFFFF, w, off);
        if (threadIdx.x == 0) {
            g_partials[blockIdx.x] = w;
            __threadfence();
            const int ticket = atomicAdd(&g_counter, 1);
            s_is_last = (ticket == NBLOCKS - 1);
        }
    }
    __syncthreads();

    // ---- last block: fixed-order final reduction (deterministic) ----
    if (s_is_last) {
        float sacc = 0.0f;
        #pragma unroll
        for (int i = threadIdx.x; i < NBLOCKS; i += THREADS)   // 8 fixed-order adds
            sacc += g_partials[i];
        sdata[threadIdx.x] = sacc;
        __syncthreads();
        #pragma unroll
        for (int stride = THREADS/2; stride >= 32; stride >>= 1) {
            if (threadIdx.x < stride) sdata[threadIdx.x] += sdata[threadIdx.x + stride];
            __syncthreads();
        }
        if (threadIdx.x < 32) {
            float w = sdata[threadIdx.x];
            #pragma unroll
            for (int off = 16; off > 0; off >>= 1)
                w += __shfl_down_sync(0xFFFFFFFF, w, off);
            if (threadIdx.x == 0) {
                out[0] = w / (float)(BB * PP);
                g_counter = 0;   // reset for next graph replay
            }
        }
    }
}

// ---------------------------------------------------------------------------
// Inputs (metadata order = setup_inputs dict order):
//   d_in[0] voxel          (B, G, G, G)   float32
//   d_in[1] points         (B, N, 3)      float32
//   d_in[2] closest_points (B, G^3, 3)    float32
//   d_in[3] planes         (B, P, 4)      float32
// Output: scalar float32
// ---------------------------------------------------------------------------
extern "C" void kernel_launch(void* const* d_in, const int* in_sizes, int n_in,
                              void* d_out, int out_size)
{
    const float* voxel  = (const float*)d_in[0];
    const float* points = (const float*)d_in[1];
    const float* cp     = (const float*)d_in[2];
    const float* planes = (const float*)d_in[3];
    float* out = (float*)d_out;

    sym_plane_loss_kernel<<<NBLOCKS, THREADS>>>(voxel, points, cp, planes, out);
}

// round 10
// speedup vs baseline: 1.1523x; 1.1523x over previous
#include <cuda_runtime.h>
#include <cuda_bf16.h>

// Problem constants
#define BB 8
#define NN 65536
#define PP 12
#define GG 64
#define G3 (GG*GG*GG)               // 262144
#define THREADS 256
#define NBLOCKS ((BB*NN)/THREADS)   // 2048
#define NCELLS  (BB*G3)             // 2097152

// Scratch (static device arrays — no dynamic allocation anywhere)
__device__ float4 g_packed[NCELLS];   // (cp.x, cp.y, cp.z, 1-voxel) per cell; 32MB
__device__ float  g_partials[NBLOCKS];
__device__ int    g_counter = 0;      // last-block ticket; self-resets each launch

// ---------------------------------------------------------------------------
// Kernel 1 (prep): pack (cp, mask) into one 16B row per cell.
// Fully coalesced streams: read voxel (4B/thr) + cp (12B/thr), write 16B/thr.
// mask = 1 - v is exact (v in {0,1}).
// ---------------------------------------------------------------------------
__global__ __launch_bounds__(THREADS)
void pack_kernel(const float* __restrict__ voxel,
                 const float* __restrict__ cp)
{
    const int c = blockIdx.x * THREADS + threadIdx.x;   // 0 .. NCELLS-1
    const float v  = voxel[c];
    const float cx = cp[c*3 + 0];
    const float cy = cp[c*3 + 1];
    const float cz = cp[c*3 + 2];
    g_packed[c] = make_float4(cx, cy, cz, 1.0f - v);
}

// ---------------------------------------------------------------------------
// Kernel 2 (main): one thread per (b, point); each thread owns the 12 flat
// positions f = pt*12+k of the reference's (b, p*n) flattening, so
// plane = f >> 16 (N = 2^16) — reproduces the reference's reshape
// reinterpretation of the broadcast (b,n,p,3) array into (b,p,n,3).
//
// ONE unconditional LDG.128 per (pt,plane): the packed row holds cp and the
// {0,1} mask, and a 16B-aligned row always occupies exactly one 32B L2
// sector. Sector traffic per (pt,plane): ~2.0 -> 1.0 (the R7-R9 invariant
// ~30us was L2-sector-bandwidth in warm-L2 timed mode).
//
// term = (dx^2+dy^2+dz^2) * mask, mask in {0,1} exactly == conditional skip.
//
// Planes normalized once per block in shared with EXACT reference arithmetic
// (sqrtf + division) — R5 proved approximate normalization flips ceil cells.
// Reflection recomputed at consume time from the same shared values with the
// same expression (bit-identical; validated R8/R9).
// ---------------------------------------------------------------------------
__global__ __launch_bounds__(THREADS, 6)
void sym_plane_loss_kernel(const float* __restrict__ points,
                           const float* __restrict__ planes,
                           float* __restrict__ out)
{
    const int t  = blockIdx.x * THREADS + threadIdx.x;   // 0 .. B*N-1
    const int b  = t >> 16;            // N = 65536; constant within a block
    const int pt = t & 0xFFFF;

    // ---- normalize this batch's 12 planes into shared (exact math) ----
    __shared__ float4 s_planes[PP];
    if (threadIdx.x < PP) {
        const int i = b * PP + threadIdx.x;
        const float nx = planes[i*4+0];
        const float ny = planes[i*4+1];
        const float nz = planes[i*4+2];
        const float d  = planes[i*4+3];
        const float norm = sqrtf(nx*nx + ny*ny + nz*nz);
        s_planes[threadIdx.x] = make_float4(nx/norm, ny/norm, nz/norm, d/norm);
    }
    __syncthreads();

    const float px = __ldg(points + t*3 + 0);
    const float py = __ldg(points + t*3 + 1);
    const float pz = __ldg(points + t*3 + 2);

    const float4* __restrict__ pk_b = g_packed + b * G3;
    const int base_f = pt * PP;

    int idxs[PP];

    // ---- Phase A: reflections -> cell indices (ALU only) ----
    #pragma unroll
    for (int k = 0; k < PP; k++) {
        const int f     = base_f + k;
        const float4 n4 = s_planes[f >> 16];

        const float dot = px*n4.x + py*n4.y + pz*n4.z;
        const float s   = 2.0f * (dot + n4.w);
        const float rx  = px - s * n4.x;
        const float ry  = py - s * n4.y;
        const float rz  = pz - s * n4.z;

        const int ix = (int)ceilf(__fadd_rn(__fmul_rn(__fadd_rn(rx, 0.5f), (float)GG), -0.5f));
        const int iy = (int)ceilf(__fadd_rn(__fmul_rn(__fadd_rn(ry, 0.5f), (float)GG), -0.5f));
        const int iz = (int)ceilf(__fadd_rn(__fmul_rn(__fadd_rn(rz, 0.5f), (float)GG), -0.5f));

        int idx = ix * (GG*GG) + iy * GG + iz;
        idx = min(max(idx, 0), G3 - 1);
        idxs[k] = idx;
    }

    // ---- Phase B: 12 unconditional packed gathers + accumulate.
    //      Two half-batches of 6 keep live regs bounded while giving MLP=6
    //      per wave (plus cross-warp concurrency). ----
    float acc = 0.0f;
    #pragma unroll
    for (int h = 0; h < 2; h++) {
        float4 q[6];
        #pragma unroll
        for (int j = 0; j < 6; j++) {
            q[j] = __ldg(pk_b + idxs[h*6 + j]);
        }
        #pragma unroll
        for (int j = 0; j < 6; j++) {
            const int k     = h*6 + j;
            const int f     = base_f + k;
            const float4 n4 = s_planes[f >> 16];
            const float dot = px*n4.x + py*n4.y + pz*n4.z;   // identical expr as Phase A
            const float s   = 2.0f * (dot + n4.w);
            const float rx  = px - s * n4.x;
            const float ry  = py - s * n4.y;
            const float rz  = pz - s * n4.z;

            const float dx = rx - q[j].x;
            const float dy = ry - q[j].y;
            const float dz = rz - q[j].z;
            acc += (dx*dx + dy*dy + dz*dz) * q[j].w;   // mask in {0,1}: exact
        }
    }

    // ---- deterministic block reduction ----
    __shared__ float sdata[THREADS];
    __shared__ bool  s_is_last;
    sdata[threadIdx.x] = acc;
    __syncthreads();
    #pragma unroll
    for (int stride = THREADS/2; stride >= 32; stride >>= 1) {
        if (threadIdx.x < stride) sdata[threadIdx.x] += sdata[threadIdx.x + stride];
        __syncthreads();
    }
    if (threadIdx.x < 32) {
        float w = sdata[threadIdx.x];
        #pragma unroll
        for (int off = 16; off > 0; off >>= 1)
            w += __shfl_down_sync(0xFFFFFFFF, w, off);
        if (threadIdx.x == 0) {
            g_partials[blockIdx.x] = w;
            __threadfence();
            const int ticket = atomicAdd(&g_counter, 1);
            s_is_last = (ticket == NBLOCKS - 1);
        }
    }
    __syncthreads();

    // ---- last block: fixed-order final reduction (deterministic) ----
    if (s_is_last) {
        float sacc = 0.0f;
        #pragma unroll
        for (int i = threadIdx.x; i < NBLOCKS; i += THREADS)   // 8 fixed-order adds
            sacc += g_partials[i];
        sdata[threadIdx.x] = sacc;
        __syncthreads();
        #pragma unroll
        for (int stride = THREADS/2; stride >= 32; stride >>= 1) {
            if (threadIdx.x < stride) sdata[threadIdx.x] += sdata[threadIdx.x + stride];
            __syncthreads();
        }
        if (threadIdx.x < 32) {
            float w = sdata[threadIdx.x];
            #pragma unroll
            for (int off = 16; off > 0; off >>= 1)
                w += __shfl_down_sync(0xFFFFFFFF, w, off);
            if (threadIdx.x == 0) {
                out[0] = w / (float)(BB * PP);
                g_counter = 0;   // reset for next graph replay
            }
        }
    }
}

// ---------------------------------------------------------------------------
// Inputs (metadata order = setup_inputs dict order):
//   d_in[0] voxel          (B, G, G, G)   float32
//   d_in[1] points         (B, N, 3)      float32
//   d_in[2] closest_points (B, G^3, 3)    float32
//   d_in[3] planes         (B, P, 4)      float32
// Output: scalar float32
// ---------------------------------------------------------------------------
extern "C" void kernel_launch(void* const* d_in, const int* in_sizes, int n_in,
                              void* d_out, int out_size)
{
    const float* voxel  = (const float*)d_in[0];
    const float* points = (const float*)d_in[1];
    const float* cp     = (const float*)d_in[2];
    const float* planes = (const float*)d_in[3];
    float* out = (float*)d_out;

    pack_kernel<<<NCELLS/THREADS, THREADS>>>(voxel, cp);
    sym_plane_loss_kernel<<<NBLOCKS, THREADS>>>(points, planes, out);
}